// round 2
// baseline (speedup 1.0000x reference)
#include <cuda_runtime.h>
#include <math.h>

// Problem constants
#define T_LEN    2048
#define N_BATCH  16
#define C_CH     64
#define NSCALES  5
#define LMAX     5377            // 16*336 + 1
#define PAD      2689            // (LMAX+1)/2
#define XS_LEN   (T_LEN + 2*PAD) // 7426
#define MAX_TAPS 1280

__constant__ int c_widths[NSCALES] = {1, 27, 76, 167, 336};

__device__ double g_int_psi[1024];
__device__ int2   g_taps[NSCALES][MAX_TAPS];  // .x = offset (t-relative), .y = float bits of weight
__device__ int    g_cnt[NSCALES];

// ---------------------------------------------------------------------------
// Stage 1: integrated Morlet wavelet, replicating pywt/numpy bit-for-bit-ish.
//   t = linspace(-8, 8, 1024): t[i] = fl(i*delta) + (-8), t[1023] = 8.0
//   step = t[1] - t[0]  (NOT exactly 16/1023 — matters for the floor() below)
//   int_psi = cumsum(psi) * step  (serial cumsum in fp64 like numpy)
// __d*_rn intrinsics prevent any fast-math folding of the step expression.
// ---------------------------------------------------------------------------
__global__ void k_psi() {
    __shared__ double ps[1024];
    int i = threadIdx.x;
    double delta = 16.0 / 1023.0;
    double t = (i == 1023) ? 8.0 : __dadd_rn(__dmul_rn((double)i, delta), -8.0);
    ps[i] = __dmul_rn(exp(__dmul_rn(-0.5, __dmul_rn(t, t))), cos(__dmul_rn(5.0, t)));
    __syncthreads();
    if (i == 0) {
        double t1   = __dadd_rn(__dmul_rn(1.0, delta), -8.0);
        double step = __dsub_rn(t1, -8.0);
        double a = 0.0;
        for (int k = 0; k < 1024; ++k) {
            a = __dadd_rn(a, ps[k]);
            g_int_psi[k] = __dmul_rn(a, step);
        }
    }
}

// ---------------------------------------------------------------------------
// Stage 2: per-scale sparse tap tables.
//   f[l] = float(int_psi[trunc(l / (scale*step))]),  l in [0, Lf)
//   h[l] = f[l-1] - f[l], l in [0, Lf]  (f[-1] = f[Lf] = 0)
//   out[t] = sum_l h[l] * x[t + l - center],  center = Lf-1-(Lf-2)/2
//   Only nonzero h are stored (h == 0 exactly when j doesn't jump).
//   -sqrt(scale) folded into the weights.
// Deterministic compaction: chunked per-thread + serial prefix sum.
// ---------------------------------------------------------------------------
__global__ void k_taps() {
    __shared__ int s_cnt[1024];
    __shared__ int s_off[1024];
    __shared__ int s_Lf;
    int s   = blockIdx.x;
    int tid = threadIdx.x;
    int scale = c_widths[s];

    double delta = 16.0 / 1023.0;
    double step  = __dsub_rn(__dadd_rn(__dmul_rn(1.0, delta), -8.0), -8.0);
    double sstep = __dmul_rn((double)scale, step);
    int Lmax = scale * 16;

    if (tid == 0) {
        long long jm = (long long)(__ddiv_rn((double)Lmax, sstep));
        int Lf;
        if (jm < 1024) {
            Lf = Lmax + 1;
        } else {
            int lo = 0, hi = Lmax;
            while (lo < hi) {
                int mid = (lo + hi) >> 1;
                long long j = (long long)(__ddiv_rn((double)mid, sstep));
                if (j >= 1024) hi = mid; else lo = mid + 1;
            }
            Lf = lo;
        }
        s_Lf = Lf;
    }
    __syncthreads();
    int Lf = s_Lf;
    int total  = Lf + 1;                 // h indices 0..Lf
    int chunk  = (total + 1023) >> 10;   // <= 6
    int l0 = tid * chunk;
    int l1 = min(l0 + chunk, total);

    int lo_cut = (Lf - 2) / 2;
    int center = Lf - 1 - lo_cut;
    float negs = (float)(-sqrt((double)scale));

    float lw[8];
    int   loff[8];
    int   lc = 0;
    for (int l = l0; l < l1; ++l) {
        float fm1 = 0.0f, fcur = 0.0f;
        if (l >= 1) {
            long long j = (long long)(__ddiv_rn((double)(l - 1), sstep));
            fm1 = (float)g_int_psi[j];
        }
        if (l < Lf) {
            long long j = (long long)(__ddiv_rn((double)l, sstep));
            fcur = (float)g_int_psi[j];
        }
        float h = fm1 - fcur;
        if (h != 0.0f) {
            lw[lc]   = h * negs;
            loff[lc] = l - center;
            ++lc;
        }
    }
    s_cnt[tid] = lc;
    __syncthreads();
    if (tid == 0) {
        int a = 0;
        for (int i = 0; i < 1024; ++i) { s_off[i] = a; a += s_cnt[i]; }
        g_cnt[s] = (a > MAX_TAPS) ? MAX_TAPS : a;
    }
    __syncthreads();
    int base = s_off[tid];
    for (int i = 0; i < lc; ++i) {
        int pos = base + i;
        if (pos < MAX_TAPS)
            g_taps[s][pos] = make_int2(loff[i], __float_as_int(lw[i]));
    }
}

// ---------------------------------------------------------------------------
// Stage 3: main sparse correlation.
// One block per (n, c) row. Zero-padded row in SMEM (no bounds checks in the
// hot loop). Each thread accumulates 8 outputs at t = tid + r*256
// (lane-consecutive -> conflict-free LDS). Tap (off, w) is uniform per warp
// -> one broadcast LDS.64 per tap.
// ---------------------------------------------------------------------------
__global__ void __launch_bounds__(256) k_cwt(const float* __restrict__ x,
                                             float* __restrict__ out) {
    __shared__ float xs[XS_LEN];
    __shared__ int2  taps[MAX_TAPS];

    int b = blockIdx.x;
    int n = b >> 6;
    int c = b & 63;
    int tid = threadIdx.x;

    const float* xrow = x + ((size_t)n * T_LEN) * C_CH + c;
    for (int i = tid; i < XS_LEN; i += 256) {
        int u = i - PAD;
        xs[i] = (u >= 0 && u < T_LEN) ? xrow[(size_t)u * C_CH] : 0.0f;
    }

    for (int s = 0; s < NSCALES; ++s) {
        __syncthreads();   // also guards xs fill at s==0 / taps reuse afterward
        int cnt = g_cnt[s];
        for (int i = tid; i < cnt; i += 256) taps[i] = g_taps[s][i];
        __syncthreads();

        float a0 = 0.f, a1 = 0.f, a2 = 0.f, a3 = 0.f;
        float a4 = 0.f, a5 = 0.f, a6 = 0.f, a7 = 0.f;
        const float* base = xs + PAD + tid;

        #pragma unroll 2
        for (int k = 0; k < cnt; ++k) {
            int2 tp = taps[k];
            float w = __int_as_float(tp.y);
            const float* p = base + tp.x;
            a0 = fmaf(w, p[0],    a0);
            a1 = fmaf(w, p[256],  a1);
            a2 = fmaf(w, p[512],  a2);
            a3 = fmaf(w, p[768],  a3);
            a4 = fmaf(w, p[1024], a4);
            a5 = fmaf(w, p[1280], a5);
            a6 = fmaf(w, p[1536], a6);
            a7 = fmaf(w, p[1792], a7);
        }

        size_t ob = ((((size_t)n * T_LEN + tid) * C_CH) + c) * NSCALES + s;
        const size_t st = (size_t)256 * C_CH * NSCALES;  // 81920
        out[ob]        = a0;
        out[ob + st]   = a1;
        out[ob + 2*st] = a2;
        out[ob + 3*st] = a3;
        out[ob + 4*st] = a4;
        out[ob + 5*st] = a5;
        out[ob + 6*st] = a6;
        out[ob + 7*st] = a7;
    }
}

extern "C" void kernel_launch(void* const* d_in, const int* in_sizes, int n_in,
                              void* d_out, int out_size) {
    const float* x = (const float*)d_in[0];
    float* out = (float*)d_out;
    (void)in_sizes; (void)n_in; (void)out_size;

    k_psi<<<1, 1024>>>();
    k_taps<<<NSCALES, 1024>>>();
    k_cwt<<<N_BATCH * C_CH, 256>>>(x, out);
}

// round 3
// speedup vs baseline: 2.0979x; 2.0979x over previous
#include <cuda_runtime.h>
#include <math.h>

#define T_LEN 2048
#define C_CH  64
#define NSC   5

// ---- sparse scales (167 -> si 0 / s=3, 336 -> si 1 / s=4) ----
#define PAD_SP  2689
#define XS_SP   (T_LEN + 2*PAD_SP)      // 7426
#define MAXTAPS 1088

// ---- dense scales (1, 27, 76 -> s=0,1,2), window-sliding ----
#define PAD_DN  616
#define CHUNK   1024
#define XS_DN   (CHUNK + 2*PAD_DN + 16) // 2272 (tail slack for zero-padded W)
#define WTOT    1712

__constant__ int c_widths[5] = {1, 27, 76, 167, 336};
__constant__ int c_wofs[3]   = {0, 32, 480};
__constant__ int c_wcap[3]   = {32, 448, 1232};

__device__ float g_W[WTOT];       // dense weights, zero padded front/back
__device__ int   g_rounds[3];
__device__ int   g_obase[3];
__device__ int2  g_taps[2][MAXTAPS];
__device__ int   g_cnt[2];

// ---------------------------------------------------------------------------
// Setup: psi -> parallel fp64 scan -> tap tables (sparse compacted, dense
// scattered). One block, 1024 threads. Index math (step, j = trunc(l/(s*step)))
// kept in exact fp64 with __d*_rn so fast-math can't fold it; the cumsum's
// rounding ORDER only perturbs weight values at ~1e-16 (tolerance is 1e-3),
// and the tap sparsity pattern (h==0 iff j doesn't jump) is order-invariant.
// ---------------------------------------------------------------------------
__global__ void k_setup() {
    __shared__ double ips[1024];
    __shared__ int    sc[1024];
    __shared__ int    sh_Lf;
    int tid = threadIdx.x;

    double delta = 16.0 / 1023.0;
    double step  = __dsub_rn(__dadd_rn(__dmul_rn(1.0, delta), -8.0), -8.0);

    double t = (tid == 1023) ? 8.0 : __dadd_rn(__dmul_rn((double)tid, delta), -8.0);
    ips[tid] = __dmul_rn(exp(__dmul_rn(-0.5, __dmul_rn(t, t))), cos(__dmul_rn(5.0, t)));
    __syncthreads();
    // Kogge-Stone inclusive scan (fp64)
    for (int off = 1; off < 1024; off <<= 1) {
        double a = (tid >= off) ? ips[tid - off] : 0.0;
        __syncthreads();
        ips[tid] = __dadd_rn(ips[tid], a);
        __syncthreads();
    }
    // int_psi[j] = ips[j] * step (applied at use)

    for (int i = tid; i < WTOT; i += 1024) g_W[i] = 0.f;
    __syncthreads();

    for (int s = 0; s < 5; ++s) {
        int scale = c_widths[s];
        double sstep = __dmul_rn((double)scale, step);
        int Lmax = scale * 16;

        if (tid == 0) {
            long long jm = (long long)(__ddiv_rn((double)Lmax, sstep));
            int Lf;
            if (jm < 1024) {
                Lf = Lmax + 1;
            } else {
                int lo = 0, hi = Lmax;
                while (lo < hi) {
                    int mid = (lo + hi) >> 1;
                    long long j = (long long)(__ddiv_rn((double)mid, sstep));
                    if (j >= 1024) hi = mid; else lo = mid + 1;
                }
                Lf = lo;
            }
            sh_Lf = Lf;
        }
        __syncthreads();
        int Lf = sh_Lf;
        int locut  = (Lf - 2) / 2;
        int center = Lf - 1 - locut;
        float negs = (float)(-sqrt((double)scale));
        int total  = Lf + 1;   // h indices 0..Lf

        if (s < 3) {
            // -------- dense scatter --------
            int obase = -((center + 3) & ~3);
            if (tid == 0) {
                g_obase[s]  = obase;
                g_rounds[s] = ((Lf - center - obase) >> 2) + 1;
            }
            for (int l = tid; l < total; l += 1024) {
                float fm1 = 0.f, fc = 0.f;
                if (l >= 1) {
                    long long j = (long long)(__ddiv_rn((double)(l - 1), sstep));
                    fm1 = (float)__dmul_rn(ips[j], step);
                }
                if (l < Lf) {
                    long long j = (long long)(__ddiv_rn((double)l, sstep));
                    fc = (float)__dmul_rn(ips[j], step);
                }
                float h = fm1 - fc;
                if (h != 0.f) {
                    int k = l - center - obase;
                    if (k >= 0 && k < c_wcap[s]) g_W[c_wofs[s] + k] = h * negs;
                }
            }
            __syncthreads();
        } else {
            // -------- sparse compaction (chunked + parallel int scan) --------
            int chunk = (total + 1023) >> 10;     // <= 6
            int l0 = tid * chunk;
            int l1 = min(l0 + chunk, total);
            float lw[8]; int lof[8]; int lc = 0;
            for (int l = l0; l < l1; ++l) {
                float fm1 = 0.f, fc = 0.f;
                if (l >= 1) {
                    long long j = (long long)(__ddiv_rn((double)(l - 1), sstep));
                    fm1 = (float)__dmul_rn(ips[j], step);
                }
                if (l < Lf) {
                    long long j = (long long)(__ddiv_rn((double)l, sstep));
                    fc = (float)__dmul_rn(ips[j], step);
                }
                float h = fm1 - fc;
                if (h != 0.f && lc < 8) { lw[lc] = h * negs; lof[lc] = l - center; ++lc; }
            }
            sc[tid] = lc;
            __syncthreads();
            for (int off = 1; off < 1024; off <<= 1) {
                int a = (tid >= off) ? sc[tid - off] : 0;
                __syncthreads();
                sc[tid] += a;
                __syncthreads();
            }
            int base = sc[tid] - lc;
            if (tid == 1023) g_cnt[s - 3] = min(sc[1023], MAXTAPS);
            for (int i = 0; i < lc; ++i) {
                int p = base + i;
                if (p < MAXTAPS) g_taps[s - 3][p] = make_int2(lof[i], __float_as_int(lw[i]));
            }
            __syncthreads();
        }
    }
}

// ---------------------------------------------------------------------------
// Main fused kernel. 4096 blocks, types interleaved by b&1 so crossbar-bound
// (sparse) and FMA-bound (dense) blocks co-reside on every SM.
//   type 0 (sparse): u -> (row = u>>1, si = u&1 in {167,336}); full row,
//     8 accumulators at stride 256, 1 LDS.32 per MAC.
//   type 1 (dense):  u -> (row = u>>1, half = u&1); 1024-output chunk, each
//     thread 4 consecutive outputs; per round: 1 coalesced LDS.128 of x,
//     1 broadcast LDS.128 of 4 dense weights, 16 FMA -> 1 B/MAC.
// ---------------------------------------------------------------------------
__global__ void __launch_bounds__(256) k_main(const float* __restrict__ x,
                                              float* __restrict__ out) {
    __shared__ __align__(16) float s_xs[XS_SP];
    __shared__ __align__(16) int2  s_tp[MAXTAPS];

    int b   = blockIdx.x;
    int tid = threadIdx.x;
    int type = b & 1;
    int u = b >> 1;
    int row = u >> 1;
    int n = row >> 6, c = row & 63;
    const float* xrow = x + (size_t)n * T_LEN * C_CH + c;

    if (type == 0) {
        // ================= sparse path (scales 167, 336) =================
        int si = u & 1;
        for (int i = tid; i < XS_SP; i += 256) {
            int g = i - PAD_SP;
            s_xs[i] = (g >= 0 && g < T_LEN) ? xrow[(size_t)g * C_CH] : 0.f;
        }
        int cnt = g_cnt[si];
        for (int i = tid; i < cnt; i += 256) s_tp[i] = g_taps[si][i];
        __syncthreads();

        float a0=0.f,a1=0.f,a2=0.f,a3=0.f,a4=0.f,a5=0.f,a6=0.f,a7=0.f;
        const float* base = s_xs + PAD_SP + tid;
        #pragma unroll 2
        for (int k = 0; k < cnt; ++k) {
            int2 tp = s_tp[k];
            float w = __int_as_float(tp.y);
            const float* p = base + tp.x;
            a0 = fmaf(w, p[0],    a0);
            a1 = fmaf(w, p[256],  a1);
            a2 = fmaf(w, p[512],  a2);
            a3 = fmaf(w, p[768],  a3);
            a4 = fmaf(w, p[1024], a4);
            a5 = fmaf(w, p[1280], a5);
            a6 = fmaf(w, p[1536], a6);
            a7 = fmaf(w, p[1792], a7);
        }
        size_t ob = (((size_t)n * T_LEN + tid) * C_CH + c) * NSC + (3 + si);
        const size_t st = (size_t)256 * C_CH * NSC;
        out[ob]        = a0;
        out[ob + st]   = a1;
        out[ob + 2*st] = a2;
        out[ob + 3*st] = a3;
        out[ob + 4*st] = a4;
        out[ob + 5*st] = a5;
        out[ob + 6*st] = a6;
        out[ob + 7*st] = a7;
    } else {
        // ================= dense window path (scales 1, 27, 76) ==========
        int half = u & 1;
        int tbase = half * CHUNK;
        for (int i = tid; i < XS_DN; i += 256) {
            int g = tbase + i - PAD_DN;
            s_xs[i] = (g >= 0 && g < T_LEN) ? xrow[(size_t)g * C_CH] : 0.f;
        }
        float* sW = (float*)(void*)s_tp;
        for (int i = tid; i < WTOT; i += 256) sW[i] = g_W[i];
        __syncthreads();

        const float4* xq = (const float4*)s_xs;
        int t0 = 4 * tid;
        #pragma unroll
        for (int s = 0; s < 3; ++s) {
            int wofs   = c_wofs[s];
            int obase  = g_obase[s];
            int rounds = g_rounds[s];
            int qb = (t0 + obase + PAD_DN) >> 2;   // always a whole quad index

            float ax=0.f, ay=0.f, az=0.f, aw=0.f;
            float4 a = xq[qb];
            #pragma unroll 2
            for (int j = 0; j < rounds; ++j) {
                float4 w  = *(const float4*)(sW + wofs + 4*j);  // uniform broadcast
                float4 bq = xq[qb + j + 1];
                ax = fmaf(w.x,a.x, fmaf(w.y,a.y, fmaf(w.z,a.z,  fmaf(w.w,a.w,  ax))));
                ay = fmaf(w.x,a.y, fmaf(w.y,a.z, fmaf(w.z,a.w,  fmaf(w.w,bq.x, ay))));
                az = fmaf(w.x,a.z, fmaf(w.y,a.w, fmaf(w.z,bq.x, fmaf(w.w,bq.y, az))));
                aw = fmaf(w.x,a.w, fmaf(w.y,bq.x,fmaf(w.z,bq.y, fmaf(w.w,bq.z, aw))));
                a = bq;
            }
            size_t ob = (((size_t)n * T_LEN + tbase + t0) * C_CH + c) * NSC + s;
            const size_t st = (size_t)C_CH * NSC;  // 320
            out[ob]        = ax;
            out[ob + st]   = ay;
            out[ob + 2*st] = az;
            out[ob + 3*st] = aw;
        }
    }
}

extern "C" void kernel_launch(void* const* d_in, const int* in_sizes, int n_in,
                              void* d_out, int out_size) {
    const float* x = (const float*)d_in[0];
    float* out = (float*)d_out;
    (void)in_sizes; (void)n_in; (void)out_size;

    k_setup<<<1, 1024>>>();
    k_main<<<4096, 256>>>(x, out);
}

// round 4
// speedup vs baseline: 2.2858x; 1.0896x over previous
#include <cuda_runtime.h>
#include <math.h>

#define T_LEN 2048
#define C_CH  64
#define NSC   5

// ---- sparse scale: 336 only (s=4) ----
#define PAD_SP  2689
#define XS_SP   (T_LEN + 2*PAD_SP)      // 7426
#define MAXTAPS 1088

// ---- dense scales (1, 27, 76, 167 -> s=0..3), window-sliding quads ----
#define PAD_DN  1344
#define CHUNK   1024
#define XS_DN   (CHUNK + 2*PAD_DN + 16) // 3728
#define WTOT    4416

// shared buffer: sparse uses xs[0,7426) + taps at 7428 (2176 floats)
//                dense  uses xs[0,3728) + W  at 3728 (4416 floats)
#define BUFSZ   9604
#define TAPOFS  7428

__constant__ int c_widths[5] = {1, 27, 76, 167, 336};
__constant__ int c_wofs[4]   = {0, 32, 480, 1712};
__constant__ int c_wcap[4]   = {32, 448, 1232, 2688};

__device__ float g_W[WTOT];     // dense weights, zero padded
__device__ int   g_rounds[4];
__device__ int   g_obase[4];
__device__ int2  g_taps[MAXTAPS];   // scale 336
__device__ int   g_cnt;

// ---------------------------------------------------------------------------
// Setup: 5 blocks, one per scale; each block recomputes psi + fp64 scan
// locally (no inter-block dependency). Index math (step, j = trunc(l/(s*step)))
// in exact fp64 with __d*_rn so fast-math can't fold it. Cumsum rounding ORDER
// only perturbs weights at ~1e-16; tap positions depend only on step (exact).
// ---------------------------------------------------------------------------
__global__ void k_setup() {
    __shared__ double ips[1024];
    __shared__ int    sc[1024];
    __shared__ int    sh_Lf;
    int tid = threadIdx.x;
    int s   = blockIdx.x;          // 0..4
    int scale = c_widths[s];

    double delta = 16.0 / 1023.0;
    double step  = __dsub_rn(__dadd_rn(__dmul_rn(1.0, delta), -8.0), -8.0);

    double t = (tid == 1023) ? 8.0 : __dadd_rn(__dmul_rn((double)tid, delta), -8.0);
    ips[tid] = __dmul_rn(exp(__dmul_rn(-0.5, __dmul_rn(t, t))), cos(__dmul_rn(5.0, t)));
    __syncthreads();
    for (int off = 1; off < 1024; off <<= 1) {   // Kogge-Stone inclusive scan
        double a = (tid >= off) ? ips[tid - off] : 0.0;
        __syncthreads();
        ips[tid] = __dadd_rn(ips[tid], a);
        __syncthreads();
    }

    double sstep = __dmul_rn((double)scale, step);
    int Lmax = scale * 16;

    if (tid == 0) {
        long long jm = (long long)(__ddiv_rn((double)Lmax, sstep));
        int Lf;
        if (jm < 1024) {
            Lf = Lmax + 1;
        } else {
            int lo = 0, hi = Lmax;
            while (lo < hi) {
                int mid = (lo + hi) >> 1;
                long long j = (long long)(__ddiv_rn((double)mid, sstep));
                if (j >= 1024) hi = mid; else lo = mid + 1;
            }
            Lf = lo;
        }
        sh_Lf = Lf;
    }
    __syncthreads();
    int Lf = sh_Lf;
    int locut  = (Lf - 2) / 2;
    int center = Lf - 1 - locut;
    float negs = (float)(-sqrt((double)scale));
    int total  = Lf + 1;               // h indices 0..Lf

    if (s < 4) {
        // -------- dense scatter into g_W --------
        int obase = -((center + 3) & ~3);
        if (tid == 0) {
            g_obase[s]  = obase;
            g_rounds[s] = ((Lf - center - obase) >> 2) + 1;
        }
        for (int i = tid; i < c_wcap[s]; i += 1024) g_W[c_wofs[s] + i] = 0.f;
        __syncthreads();
        for (int l = tid; l < total; l += 1024) {
            float fm1 = 0.f, fc = 0.f;
            if (l >= 1) {
                long long j = (long long)(__ddiv_rn((double)(l - 1), sstep));
                fm1 = (float)__dmul_rn(ips[j], step);
            }
            if (l < Lf) {
                long long j = (long long)(__ddiv_rn((double)l, sstep));
                fc = (float)__dmul_rn(ips[j], step);
            }
            float h = fm1 - fc;
            if (h != 0.f) {
                int k = l - center - obase;
                if (k >= 0 && k < c_wcap[s]) g_W[c_wofs[s] + k] = h * negs;
            }
        }
    } else {
        // -------- sparse compaction (chunked + parallel int scan) --------
        int chunk = (total + 1023) >> 10;     // 6 for scale 336
        int l0 = tid * chunk;
        int l1 = min(l0 + chunk, total);
        float lw[8]; int lof[8]; int lc = 0;
        for (int l = l0; l < l1; ++l) {
            float fm1 = 0.f, fc = 0.f;
            if (l >= 1) {
                long long j = (long long)(__ddiv_rn((double)(l - 1), sstep));
                fm1 = (float)__dmul_rn(ips[j], step);
            }
            if (l < Lf) {
                long long j = (long long)(__ddiv_rn((double)l, sstep));
                fc = (float)__dmul_rn(ips[j], step);
            }
            float h = fm1 - fc;
            if (h != 0.f && lc < 8) { lw[lc] = h * negs; lof[lc] = l - center; ++lc; }
        }
        sc[tid] = lc;
        __syncthreads();
        for (int off = 1; off < 1024; off <<= 1) {
            int a = (tid >= off) ? sc[tid - off] : 0;
            __syncthreads();
            sc[tid] += a;
            __syncthreads();
        }
        int base = sc[tid] - lc;
        if (tid == 1023) g_cnt = min(sc[1023], MAXTAPS);
        for (int i = 0; i < lc; ++i) {
            int p = base + i;
            if (p < MAXTAPS) g_taps[p] = make_int2(lof[i], __float_as_int(lw[i]));
        }
    }
}

// ---------------------------------------------------------------------------
// Main fused kernel. 3072 blocks: row = b/3, phase = b%3.
//   phase 0 (sparse, scale 336): full row, 8 accumulators at stride 256,
//     1 LDS.32 per MAC (crossbar-bound: taps have gaps 5-6, no reuse possible).
//   phase 1/2 (dense, scales 1,27,76,167; half = phase-1): 1024-output chunk,
//     4 consecutive outputs/thread; per round 1 LDS.128 x + broadcast w quad
//     + 16 FMA -> ~1 B/MAC (FMA-bound). Phase interleave mixes both kinds
//     on every SM so crossbar and FMA pipes overlap.
// ---------------------------------------------------------------------------
__global__ void __launch_bounds__(256) k_main(const float* __restrict__ x,
                                              float* __restrict__ out) {
    __shared__ __align__(16) float s_buf[BUFSZ];

    int b   = blockIdx.x;
    int tid = threadIdx.x;
    int row   = b / 3;
    int phase = b - 3 * row;
    int n = row >> 6, c = row & 63;
    const float* xrow = x + (size_t)n * T_LEN * C_CH + c;

    if (phase == 0) {
        // ================= sparse path (scale 336) =================
        float* xs = s_buf;
        int2*  tp = (int2*)(s_buf + TAPOFS);
        for (int i = tid; i < XS_SP; i += 256) {
            int g = i - PAD_SP;
            xs[i] = (g >= 0 && g < T_LEN) ? xrow[(size_t)g * C_CH] : 0.f;
        }
        int cnt = g_cnt;
        for (int i = tid; i < cnt; i += 256) tp[i] = g_taps[i];
        __syncthreads();

        float a0=0.f,a1=0.f,a2=0.f,a3=0.f,a4=0.f,a5=0.f,a6=0.f,a7=0.f;
        const float* base = xs + PAD_SP + tid;
        #pragma unroll 2
        for (int k = 0; k < cnt; ++k) {
            int2 t2 = tp[k];
            float w = __int_as_float(t2.y);
            const float* p = base + t2.x;
            a0 = fmaf(w, p[0],    a0);
            a1 = fmaf(w, p[256],  a1);
            a2 = fmaf(w, p[512],  a2);
            a3 = fmaf(w, p[768],  a3);
            a4 = fmaf(w, p[1024], a4);
            a5 = fmaf(w, p[1280], a5);
            a6 = fmaf(w, p[1536], a6);
            a7 = fmaf(w, p[1792], a7);
        }
        size_t ob = (((size_t)n * T_LEN + tid) * C_CH + c) * NSC + 4;
        const size_t st = (size_t)256 * C_CH * NSC;
        out[ob]        = a0;
        out[ob + st]   = a1;
        out[ob + 2*st] = a2;
        out[ob + 3*st] = a3;
        out[ob + 4*st] = a4;
        out[ob + 5*st] = a5;
        out[ob + 6*st] = a6;
        out[ob + 7*st] = a7;
    } else {
        // ================= dense window path (scales 1, 27, 76, 167) =====
        int tbase = (phase - 1) * CHUNK;
        float* xs = s_buf;
        float* sW = s_buf + XS_DN;
        for (int i = tid; i < XS_DN; i += 256) {
            int g = tbase + i - PAD_DN;
            xs[i] = (g >= 0 && g < T_LEN) ? xrow[(size_t)g * C_CH] : 0.f;
        }
        for (int i = tid; i < WTOT; i += 256) sW[i] = g_W[i];
        __syncthreads();

        const float4* xq = (const float4*)xs;
        int t0 = 4 * tid;
        #pragma unroll
        for (int s = 0; s < 4; ++s) {
            int wofs   = c_wofs[s];
            int obase  = g_obase[s];
            int rounds = g_rounds[s];
            int qb = (t0 + obase + PAD_DN) >> 2;   // whole quad index by construction

            float ax=0.f, ay=0.f, az=0.f, aw=0.f;
            float4 a = xq[qb];
            #pragma unroll 2
            for (int j = 0; j < rounds; ++j) {
                float4 w  = *(const float4*)(sW + wofs + 4*j);  // uniform broadcast
                float4 bq = xq[qb + j + 1];
                ax = fmaf(w.x,a.x, fmaf(w.y,a.y, fmaf(w.z,a.z,  fmaf(w.w,a.w,  ax))));
                ay = fmaf(w.x,a.y, fmaf(w.y,a.z, fmaf(w.z,a.w,  fmaf(w.w,bq.x, ay))));
                az = fmaf(w.x,a.z, fmaf(w.y,a.w, fmaf(w.z,bq.x, fmaf(w.w,bq.y, az))));
                aw = fmaf(w.x,a.w, fmaf(w.y,bq.x,fmaf(w.z,bq.y, fmaf(w.w,bq.z, aw))));
                a = bq;
            }
            size_t ob = (((size_t)n * T_LEN + tbase + t0) * C_CH + c) * NSC + s;
            const size_t st = (size_t)C_CH * NSC;  // 320
            out[ob]        = ax;
            out[ob + st]   = ay;
            out[ob + 2*st] = az;
            out[ob + 3*st] = aw;
        }
    }
}

extern "C" void kernel_launch(void* const* d_in, const int* in_sizes, int n_in,
                              void* d_out, int out_size) {
    const float* x = (const float*)d_in[0];
    float* out = (float*)d_out;
    (void)in_sizes; (void)n_in; (void)out_size;

    k_setup<<<5, 1024>>>();
    k_main<<<3072, 256>>>(x, out);
}